// round 17
// baseline (speedup 1.0000x reference)
#include <cuda_runtime.h>

typedef unsigned long long u64;

#define H_      51
#define TSTEPS  512
#define BTOT    1024
#define NB      8
#define NBLK    (BTOT / NB)       // 128 blocks
#define NTHR    512
#define GP      224               // padded gate slots (gate-major, like R12)
#define HROW    108               // h row: [h1(51)|pad|h2(51)|pad..]
#define HC      (HROW/4)          // 27 ulonglong2 per h row
#define PRB     228               // partial per-batch stride (conflict-free)
#define LVLSZ   (NB * PRB)        // 1824
#define L1LV    3
#define L2LV    3

// ---- shared memory layout (float offsets) ----
#define OFF_W1   0                          // [13][224][4]
#define OFF_W2   (OFF_W1 + 13*GP*4)         // [26][224][4]
#define OFF_XS   (OFF_W2 + 26*GP*4)         // [512][8]
#define OFF_HS   (OFF_XS + TSTEPS*8)        // [8][108]
#define OFF_C1   (OFF_HS + NB*HROW)         // [8][52]
#define OFF_C2   (OFF_C1 + NB*52)           // [8][52]
#define OFF_PB1  (OFF_C2 + NB*52)           // 3 levels x [8][228]
#define OFF_PB2  (OFF_PB1 + L1LV*LVLSZ)     // 3 levels x [8][228]
#define OFF_B1   (OFF_PB2 + L2LV*LVLSZ)     // 224
#define OFF_B2   (OFF_B1 + GP)              // 224
#define OFF_WI1  (OFF_B2 + GP)              // 224
#define OFF_WL   (OFF_WI1 + GP)             // 56
#define OFF_BL   (OFF_WL + 56)              // 4
#define SMEM_FLOATS (OFF_BL + 4)
#define SMEM_BYTES  (SMEM_FLOATS * 4)       // ~205 KB

__device__ __forceinline__ void ffma2(u64 &d, u64 a, u64 b) {
    asm("fma.rn.f32x2 %0, %1, %2, %0;" : "+l"(d) : "l"(a), "l"(b));
}
__device__ __forceinline__ float2 unpk(u64 v) {
    float2 r;
    asm("mov.b64 {%0, %1}, %2;" : "=f"(r.x), "=f"(r.y) : "l"(v));
    return r;
}
__device__ __forceinline__ float sigf(float x) {
    return __fdividef(1.0f, 1.0f + __expf(-x));
}
__device__ __forceinline__ float tanhfast(float x) {
    return __fdividef(2.0f, 1.0f + __expf(-2.0f * x)) - 1.0f;
}

// One gemv segment: layer ISL2, slot-group offset JOFF (64*jg), k-chunks
// [K0, K0+CNT), partial level LVL, NJ j-subgroups, optional x-term.
// Warp covers ALL 8 batches (w loaded ONCE per chunk per j); acc[NJ][8]
// with NJ<=2 keeps registers at ~32 for accumulators.
template<int ISL2, int JOFF, int K0, int CNT, int LVL, int NJ, bool ADDX>
__device__ __forceinline__ void seg(float* sm, int lane, const float* xrow)
{
    const ulonglong2* __restrict__ wp =
        (const ulonglong2*)(sm + (ISL2 ? OFF_W2 : OFF_W1)) + K0 * GP + lane + JOFF;
    const ulonglong2* __restrict__ hp =
        (const ulonglong2*)(sm + OFF_HS) + K0;
    float* pb = sm + (ISL2 ? OFF_PB2 : OFF_PB1) + LVL * LVLSZ + lane + JOFF;

    u64 acc[NJ][8];
#pragma unroll
    for (int j = 0; j < NJ; j++)
#pragma unroll
        for (int b = 0; b < 8; b++) acc[j][b] = 0ull;

#pragma unroll
    for (int i = 0; i < CNT; i++) {
        ulonglong2 w[NJ];
#pragma unroll
        for (int j = 0; j < NJ; j++) w[j] = wp[i * GP + 32 * j];
#pragma unroll
        for (int half = 0; half < 2; half++) {
            ulonglong2 h[4];
#pragma unroll
            for (int b = 0; b < 4; b++) h[b] = hp[(half * 4 + b) * HC + i];
#pragma unroll
            for (int j = 0; j < NJ; j++)
#pragma unroll
                for (int b = 0; b < 4; b++) {
                    ffma2(acc[j][half * 4 + b], w[j].x, h[b].x);
                    ffma2(acc[j][half * 4 + b], w[j].y, h[b].y);
                }
        }
    }

    float wi[NJ];
    if (ADDX) {
#pragma unroll
        for (int j = 0; j < NJ; j++) wi[j] = sm[OFF_WI1 + lane + JOFF + 32 * j];
    }
#pragma unroll
    for (int b = 0; b < 8; b++) {
        float xv = ADDX ? xrow[b] : 0.0f;
#pragma unroll
        for (int j = 0; j < NJ; j++) {
            float2 p = unpk(acc[j][b]);
            float gv = p.x + p.y;
            if (ADDX) gv = fmaf(xv, wi[j], gv);
            pb[b * PRB + 32 * j] = gv;
        }
    }
}

// merged pointwise update: U2(t) + U1(t+1), 408 jobs (tid<408), scalar
// conflict-free reads, 3 levels per layer.
__device__ __forceinline__ void cell_update(float* sm, int tid,
                                            bool doU2, bool doU1)
{
    if (tid < NB * H_) {
        int b = tid & 7, u = tid >> 3;
        if (doU2) {
            const float* p2 = sm + OFF_PB2 + b * PRB + u;
            float gi = sm[OFF_B2 + u];
            float gf = sm[OFF_B2 + 51 + u];
            float gg = sm[OFF_B2 + 102 + u];
            float go = sm[OFF_B2 + 153 + u];
#pragma unroll
            for (int l = 0; l < L2LV; l++) {
                const float* p = p2 + l * LVLSZ;
                gi += p[0]; gf += p[51]; gg += p[102]; go += p[153];
            }
            float c  = sm[OFF_C2 + b * 52 + u];
            float cn = sigf(gf) * c + sigf(gi) * tanhfast(gg);
            float hn = sigf(go) * tanhfast(cn);
            sm[OFF_C2 + b * 52 + u] = cn;
            sm[OFF_HS + b * HROW + 52 + u] = hn;
        }
        if (doU1) {
            const float* p1 = sm + OFF_PB1 + b * PRB + u;
            float gi = sm[OFF_B1 + u];
            float gf = sm[OFF_B1 + 51 + u];
            float gg = sm[OFF_B1 + 102 + u];
            float go = sm[OFF_B1 + 153 + u];
#pragma unroll
            for (int l = 0; l < L1LV; l++) {
                const float* p = p1 + l * LVLSZ;
                gi += p[0]; gf += p[51]; gg += p[102]; go += p[153];
            }
            float c  = sm[OFF_C1 + b * 52 + u];
            float cn = sigf(gf) * c + sigf(gi) * tanhfast(gg);
            float hn = sigf(go) * tanhfast(cn);
            sm[OFF_C1 + b * 52 + u] = cn;
            sm[OFF_HS + b * HROW + u] = hn;
        }
    }
}

__device__ __forceinline__ void out_phase(const float* sm, int lane, int bid,
                                          int tcol, float* __restrict__ out)
{
    int ob = lane & 7, part = lane >> 3;            // 4 parts x 13 k
    float a = 0.0f;
#pragma unroll
    for (int kk = 0; kk < 13; kk++) {
        int k = part * 13 + kk;                     // k=51 -> zero pad
        a = fmaf(sm[OFF_HS + ob * HROW + 52 + k], sm[OFF_WL + k], a);
    }
    a += __shfl_xor_sync(0xffffffffu, a, 8);
    a += __shfl_xor_sync(0xffffffffu, a, 16);
    if (lane < 8)
        out[(bid * NB + ob) * TSTEPS + tcol] = a + sm[OFF_BL];
}

__global__ void __launch_bounds__(NTHR, 1)
lstm_kernel(const float* __restrict__ input,
            const float* __restrict__ Wih1, const float* __restrict__ Whh1,
            const float* __restrict__ bih1, const float* __restrict__ bhh1,
            const float* __restrict__ Wih2, const float* __restrict__ Whh2,
            const float* __restrict__ bih2, const float* __restrict__ bhh2,
            const float* __restrict__ Wlin, const float* __restrict__ blin,
            float* __restrict__ out)
{
    extern __shared__ float sm[];
    const int tid  = threadIdx.x;
    const int bid  = blockIdx.x;
    const int lane = tid & 31;
    const int wid  = tid >> 5;            // 0..15

    // ---- staging (slot g = original gate row, R12-identical) ----
    for (int i = tid; i < NB * HROW; i += NTHR) sm[OFF_HS + i] = 0.0f;
    for (int i = tid; i < NB * 52 * 2; i += NTHR) sm[OFF_C1 + i] = 0.0f;
    for (int i = tid; i < TSTEPS * NB; i += NTHR) {
        int t = i >> 3, bb = i & 7;
        sm[OFF_XS + i] = input[t * BTOT + bid * NB + bb];
    }
    for (int i = tid; i < 13 * GP * 4; i += NTHR) {
        int c = i & 3, g = (i >> 2) % GP, kq = i / (GP * 4);
        int k = 4 * kq + c;
        sm[OFF_W1 + i] = (g < 204 && k < H_) ? Whh1[g * H_ + k] : 0.0f;
    }
    for (int i = tid; i < 26 * GP * 4; i += NTHR) {
        int c = i & 3, g = (i >> 2) % GP, kq = i / (GP * 4);
        int k = 4 * kq + c;
        float v = 0.0f;
        if (g < 204) {
            if (k < H_)                  v = Wih2[g * H_ + k];
            else if (k >= 52 && k < 103) v = Whh2[g * H_ + (k - 52)];
        }
        sm[OFF_W2 + i] = v;
    }
    for (int i = tid; i < GP; i += NTHR) {
        sm[OFF_B1  + i] = (i < 204) ? bih1[i] + bhh1[i] : 0.0f;
        sm[OFF_B2  + i] = (i < 204) ? bih2[i] + bhh2[i] : 0.0f;
        sm[OFF_WI1 + i] = (i < 204) ? Wih1[i] : 0.0f;
    }
    if (tid < 56) sm[OFF_WL + tid] = (tid < H_) ? Wlin[tid] : 0.0f;
    if (tid == 0) sm[OFF_BL] = blin[0];
    __syncthreads();

    // ---- warp roles: j-groups of 2 slots' worth (JOFF = 64*jg), NB=8 ----
    // L2 (t):    w0-2 jg0 lv0-2 [0,9)[9,18)[18,26); w3-5 jg1; w6-8 jg2;
    //            w12-14 jg3 (NJ1) lv0-2
    // L1 (t+1):  w9 jg0 lv0[0,5)+x, lv1[5,9); w10 jg1 same; w11 jg2 same;
    //            w12-14 jg0-2 lv2 [9,13); w15 jg3 (NJ1) lv0+x,lv1,lv2
    // out duty: w2 (lightest L2-only warp).
    auto run_l2 = [&]() {
        switch (wid) {
            case 0:  seg<1,   0,  0, 9, 0, 2, false>(sm, lane, nullptr); break;
            case 1:  seg<1,   0,  9, 9, 1, 2, false>(sm, lane, nullptr); break;
            case 2:  seg<1,   0, 18, 8, 2, 2, false>(sm, lane, nullptr); break;
            case 3:  seg<1,  64,  0, 9, 0, 2, false>(sm, lane, nullptr); break;
            case 4:  seg<1,  64,  9, 9, 1, 2, false>(sm, lane, nullptr); break;
            case 5:  seg<1,  64, 18, 8, 2, 2, false>(sm, lane, nullptr); break;
            case 6:  seg<1, 128,  0, 9, 0, 2, false>(sm, lane, nullptr); break;
            case 7:  seg<1, 128,  9, 9, 1, 2, false>(sm, lane, nullptr); break;
            case 8:  seg<1, 128, 18, 8, 2, 2, false>(sm, lane, nullptr); break;
            case 12: seg<1, 192,  0, 9, 0, 1, false>(sm, lane, nullptr); break;
            case 13: seg<1, 192,  9, 9, 1, 1, false>(sm, lane, nullptr); break;
            case 14: seg<1, 192, 18, 8, 2, 1, false>(sm, lane, nullptr); break;
            default: break;
        }
    };
    auto run_l1 = [&](const float* xr) {
        switch (wid) {
            case 9:  seg<0,   0, 0, 5, 0, 2, true >(sm, lane, xr);
                     seg<0,   0, 5, 4, 1, 2, false>(sm, lane, xr); break;
            case 10: seg<0,  64, 0, 5, 0, 2, true >(sm, lane, xr);
                     seg<0,  64, 5, 4, 1, 2, false>(sm, lane, xr); break;
            case 11: seg<0, 128, 0, 5, 0, 2, true >(sm, lane, xr);
                     seg<0, 128, 5, 4, 1, 2, false>(sm, lane, xr); break;
            case 12: seg<0,   0, 9, 4, 2, 2, false>(sm, lane, xr); break;
            case 13: seg<0,  64, 9, 4, 2, 2, false>(sm, lane, xr); break;
            case 14: seg<0, 128, 9, 4, 2, 2, false>(sm, lane, xr); break;
            case 15: seg<0, 192, 0, 5, 0, 1, true >(sm, lane, xr);
                     seg<0, 192, 5, 4, 1, 1, false>(sm, lane, xr);
                     seg<0, 192, 9, 4, 2, 1, false>(sm, lane, xr); break;
            default: break;
        }
    };

    // ---- prologue: G1(0), U1(0) ----
    run_l1(sm + OFF_XS);
    __syncthreads();
    cell_update(sm, tid, false, true);
    __syncthreads();

    // ---- pipelined recurrence ----
    for (int t = 0; t < TSTEPS; t++) {
        // phase A: G2(t) + G1(t+1) + out(t-1)
        run_l2();
        if (t + 1 < TSTEPS) run_l1(sm + OFF_XS + (t + 1) * 8);
        if (wid == 2 && t > 0) out_phase(sm, lane, bid, t - 1, out);
        __syncthreads();

        // phase B: U2(t) + U1(t+1), merged independent chains
        cell_update(sm, tid, true, t + 1 < TSTEPS);
        __syncthreads();
    }

    // ---- epilogue ----
    if (wid == 2) out_phase(sm, lane, bid, TSTEPS - 1, out);
}

extern "C" void kernel_launch(void* const* d_in, const int* in_sizes, int n_in,
                              void* d_out, int out_size)
{
    const float* input = (const float*)d_in[0];
    const float* Wih1  = (const float*)d_in[1];
    const float* Whh1  = (const float*)d_in[2];
    const float* bih1  = (const float*)d_in[3];
    const float* bhh1  = (const float*)d_in[4];
    const float* Wih2  = (const float*)d_in[5];
    const float* Whh2  = (const float*)d_in[6];
    const float* bih2  = (const float*)d_in[7];
    const float* bhh2  = (const float*)d_in[8];
    const float* Wlin  = (const float*)d_in[9];
    const float* blin  = (const float*)d_in[10];
    float* out = (float*)d_out;

    static bool attr_set = false;
    if (!attr_set) {
        cudaFuncSetAttribute(lstm_kernel,
                             cudaFuncAttributeMaxDynamicSharedMemorySize,
                             SMEM_BYTES);
        attr_set = true;
    }
    lstm_kernel<<<NBLK, NTHR, SMEM_BYTES>>>(input, Wih1, Whh1, bih1, bhh1,
                                            Wih2, Whh2, bih2, bhh2,
                                            Wlin, blin, out);
}